// round 11
// baseline (speedup 1.0000x reference)
#include <cuda_runtime.h>
#include <cstdint>

#define TT 2048
#define DD 512
#define LCH 32
#define NCH (TT / LCH)            // 64
// state kernel staging
#define SSTEPS 32                 // one chunk per block
#define SSTEP_F 96                // k~64 + v32
#define SSTAGE_F (SSTEPS * SSTEP_F)   // 3072 floats
#define SSTAGE_B (SSTAGE_F * 4)       // 12288 B
#define SNSTG 3
// ygemm tiling
#define GJ 128                    // cols per CTA
#define GK 64                     // K rows per S tile
#define RPITCH 68                 // sR row pitch (floats, 16B-aligned rows)
// ygemm smem offsets (floats)
#define YG_SS 0                           // [2][GK*GJ]     16384
#define YG_SR (YG_SS + 2 * GK * GJ)       // [2][32*RPITCH]  4352
#define YG_SV (YG_SR + 2 * 32 * RPITCH)   // [32*GJ]         4096
#define YG_SA (YG_SV + 32 * GJ)           // [32*33]         1056
#define YG_RK (YG_SA + 32 * 33)           // [32]
#define YG_FLOATS (YG_RK + 32)
#define YG_SMEM (YG_FLOATS * 4)

// scratch (device globals — no allocation allowed)
__device__ float g_chk[(size_t)NCH * DD * DD];  // 64 MB chunk-start checkpoints
__device__ float g_rt[(size_t)TT * DD];         // r~ = r * P_prev
__device__ float g_kt[(size_t)TT * DD];         // k~ = k / P
__device__ float g_pl[(size_t)NCH * DD];        // per-chunk decay P_L
__device__ float g_A[(size_t)NCH * LCH * LCH];  // masked intra-chunk A
__device__ float g_ruk[TT];

typedef unsigned long long ull;

__device__ __forceinline__ ull pk2(float lo, float hi) {
    ull r; asm("mov.b64 %0,{%1,%2};" : "=l"(r) : "f"(lo), "f"(hi)); return r;
}
__device__ __forceinline__ void up2(ull x, float& lo, float& hi) {
    asm("mov.b64 {%0,%1},%2;" : "=f"(lo), "=f"(hi) : "l"(x));
}
__device__ __forceinline__ ull f2fma(ull a, ull b, ull c) {
    ull d; asm("fma.rn.f32x2 %0,%1,%2,%3;" : "=l"(d) : "l"(a), "l"(b), "l"(c)); return d;
}
__device__ __forceinline__ ull f2mul(ull a, ull b) {
    ull d; asm("mul.rn.f32x2 %0,%1,%2;" : "=l"(d) : "l"(a), "l"(b)); return d;
}
__device__ __forceinline__ ull f2add(ull a, ull b) {
    ull d; asm("add.rn.f32x2 %0,%1,%2;" : "=l"(d) : "l"(a), "l"(b)); return d;
}

#define CP16(dst, src) asm volatile("cp.async.cg.shared.global [%0], [%1], 16;\n" :: "r"(dst), "l"(src))
#define CP_COMMIT()    asm volatile("cp.async.commit_group;\n")
#define CP_WAIT1()     asm volatile("cp.async.wait_group 1;\n" ::: "memory")

// ---------------------------------------------------------------------------
// K1: per-chunk cumulative decay; emit r~, k~, P_L. grid (NCH, 2) x 256.
// ---------------------------------------------------------------------------
__global__ void __launch_bounds__(256) wkv_pre(
    const float* __restrict__ r, const float* __restrict__ w,
    const float* __restrict__ k)
{
    const int a = blockIdx.y * 256 + threadIdx.x;
    const int c = blockIdx.x;
    const size_t base = (size_t)c * LCH * DD + a;
    float P = 1.f;
#pragma unroll 4
    for (int s = 0; s < LCH; s++) {
        const size_t idx = base + (size_t)s * DD;
        const float rv = r[idx], wv = w[idx], kv = k[idx];
        g_rt[idx] = rv * P;
        P = fmaxf(P * wv, 1e-30f);
        g_kt[idx] = kv / P;
    }
    g_pl[(size_t)c * DD + a] = P;
}

// state-kernel cp role: 24 pieces per step, 768 per block, 3 per thread
__device__ __forceinline__ void cp_role_s(
    int piece, const float* v, int bx, int by,
    const float*& src, unsigned& foff)
{
    const int stp  = piece / 24;
    const int role = piece - stp * 24;
    if (role < 16) {
        src  = g_kt + by * 64 + role * 4;
        foff = (unsigned)(stp * SSTEP_F + role * 4);
    } else {
        const int q = role - 16;
        src  = v + bx * 32 + q * 4;
        foff = (unsigned)(stp * SSTEP_F + 64 + q * 4);
    }
    src += (size_t)stp * DD;
}

// ---------------------------------------------------------------------------
// K2 (sequential): state propagation ONLY. Grid (16,8), 256 thr, 1 CTA/SM.
// Tile 64r x 32c; thread = 8 rows x 1 col as 4 f32x2 pairs.
// Per chunk (=1 block of 32 steps): write checkpoint S_c, acc += k~*v,
// then S = P_L*(S+acc). One barrier per 32 steps. No y work at all.
// ---------------------------------------------------------------------------
__global__ void __launch_bounds__(256, 1) wkv_state(
    const float* __restrict__ v, const float* __restrict__ init_state,
    float* __restrict__ state_out)
{
    __shared__ __align__(16) float stage[SNSTG * SSTAGE_F];   // 36.9 KB

    const int tid  = threadIdx.x;
    const int bx   = blockIdx.x;
    const int by   = blockIdx.y;
    const int wid  = tid >> 5;
    const int lane = tid & 31;
    const int c    = lane & 3;
    const int rg   = lane >> 2;
    const int col32 = wid * 4 + c;
    const int b    = bx * 32 + col32;
    const int a0   = by * 64 + rg * 8;

    const unsigned su = (unsigned)__cvta_generic_to_shared(stage);

    const float *s0, *s1, *s2s;
    unsigned o0, o1, o2;
    cp_role_s(tid,       v, bx, by, s0, o0);
    cp_role_s(tid + 256, v, bx, by, s1, o1);
    cp_role_s(tid + 512, v, bx, by, s2s, o2);
    o0 = su + o0 * 4u; o1 = su + o1 * 4u; o2 = su + o2 * 4u;

    const float is0 = init_state[b];
    ull s2[4], acc[4];
    {
        ull iv = pk2(is0, is0);
#pragma unroll
        for (int i = 0; i < 4; i++) { s2[i] = iv; acc[i] = 0ull; }
    }

    // prologue: blocks 0,1
    CP16(o0, s0); CP16(o1, s1); CP16(o2, s2s); CP_COMMIT();
    s0 += SSTEPS * DD; s1 += SSTEPS * DD; s2s += SSTEPS * DD;
    CP16(o0 + SSTAGE_B, s0); CP16(o1 + SSTAGE_B, s1); CP16(o2 + SSTAGE_B, s2s); CP_COMMIT();
    s0 += SSTEPS * DD; s1 += SSTEPS * DD; s2s += SSTEPS * DD;
    CP_WAIT1();
    __syncthreads();

    int gOff = 0;
    unsigned giOff = 2 * SSTAGE_B;

    for (int blk = 0; blk < NCH; blk++) {
        // checkpoint: S at chunk start
        {
            float* chk = g_chk + (size_t)blk * DD * DD;
#pragma unroll
            for (int j = 0; j < 4; j++) {
                float lo, hi; up2(s2[j], lo, hi);
                chk[(size_t)(a0 + 2 * j)     * DD + b] = lo;
                chk[(size_t)(a0 + 2 * j + 1) * DD + b] = hi;
            }
        }
        // this chunk's P_L
        ull pl2[4];
        {
            const float4* plp = (const float4*)(g_pl + (size_t)blk * DD + a0);
            float4 pa = plp[0], pb = plp[1];
            pl2[0] = pk2(pa.x, pa.y); pl2[1] = pk2(pa.z, pa.w);
            pl2[2] = pk2(pb.x, pb.y); pl2[3] = pk2(pb.z, pb.w);
        }

        const char* sgb = (const char*)stage + gOff;
#pragma unroll
        for (int st = 0; st < SSTEPS; st++) {
            const ull* sb = (const ull*)(sgb + st * (SSTEP_F * 4));
            ulonglong2 ka = *reinterpret_cast<const ulonglong2*>(sb + rg * 4);
            ulonglong2 kb = *reinterpret_cast<const ulonglong2*>(sb + rg * 4 + 2);
            const float vf = ((const float*)sb)[64 + col32];
            const ull vv = pk2(vf, vf);
            acc[0] = f2fma(ka.x, vv, acc[0]);
            acc[1] = f2fma(ka.y, vv, acc[1]);
            acc[2] = f2fma(kb.x, vv, acc[2]);
            acc[3] = f2fma(kb.y, vv, acc[3]);
        }

        // chunk end: S = P_L * (S + acc)
#pragma unroll
        for (int i = 0; i < 4; i++) {
            s2[i] = f2mul(pl2[i], f2add(s2[i], acc[i]));
            acc[i] = 0ull;
        }

        // stage block blk+2
        if (blk + 2 < NCH) { CP16(o0 + giOff, s0); CP16(o1 + giOff, s1); CP16(o2 + giOff, s2s); }
        s0 += SSTEPS * DD; s1 += SSTEPS * DD; s2s += SSTEPS * DD;
        CP_COMMIT();
        CP_WAIT1();
        __syncthreads();

        gOff  = (gOff  == (SNSTG - 1) * SSTAGE_B) ? 0 : gOff  + SSTAGE_B;
        giOff = (giOff == (SNSTG - 1) * SSTAGE_B) ? 0 : giOff + SSTAGE_B;
    }

    if (state_out) {
#pragma unroll
        for (int j = 0; j < 4; j++) {
            float lo, hi; up2(s2[j], lo, hi);
            state_out[(size_t)(a0 + 2 * j)     * DD + b] = lo;
            state_out[(size_t)(a0 + 2 * j + 1) * DD + b] = hi;
        }
    }
}

// ---------------------------------------------------------------------------
// K3: A[c][t][s] = r~_t . k~_s (strict lower triangle, else 0). grid NCH.
// ---------------------------------------------------------------------------
__global__ void __launch_bounds__(256) wkv_amat()
{
    __shared__ float sR[32][68], sK[32][68];
    const int cc = blockIdx.x;
    const int tid = threadIdx.x;
    const int t = tid >> 3, sq = (tid & 7) * 4;
    float acc[4] = {0.f, 0.f, 0.f, 0.f};

    for (int kk = 0; kk < DD; kk += 64) {
        for (int i = tid; i < 32 * 16; i += 256) {
            const int row = i >> 4, col4 = (i & 15) * 4;
            const size_t gidx = (size_t)(cc * LCH + row) * DD + kk + col4;
            *(float4*)&sR[row][col4] = *(const float4*)&g_rt[gidx];
            *(float4*)&sK[row][col4] = *(const float4*)&g_kt[gidx];
        }
        __syncthreads();
        for (int j = 0; j < 64; j++) {
            const float rv = sR[t][j];
            acc[0] += rv * sK[sq + 0][j];
            acc[1] += rv * sK[sq + 1][j];
            acc[2] += rv * sK[sq + 2][j];
            acc[3] += rv * sK[sq + 3][j];
        }
        __syncthreads();
    }
#pragma unroll
    for (int i = 0; i < 4; i++)
        g_A[(size_t)(cc * LCH + t) * LCH + sq + i] = (sq + i < t) ? acc[i] : 0.f;
}

// ---------------------------------------------------------------------------
// K4: ruk_t = sum_a r*u*k. grid TT/8 x 256 (warp per t).
// ---------------------------------------------------------------------------
__global__ void __launch_bounds__(256) wkv_ruk(
    const float* __restrict__ r, const float* __restrict__ k,
    const float* __restrict__ u)
{
    const int wid = threadIdx.x >> 5, lane = threadIdx.x & 31;
    const int t = blockIdx.x * 8 + wid;
    const float* rt = r + (size_t)t * DD;
    const float* kt = k + (size_t)t * DD;
    float p = 0.f;
#pragma unroll
    for (int i = 0; i < 16; i++) {
        const int a = lane + i * 32;
        p += rt[a] * u[a] * kt[a];
    }
#pragma unroll
    for (int m = 16; m >= 1; m >>= 1) p += __shfl_xor_sync(0xffffffffu, p, m);
    if (lane == 0) g_ruk[t] = p;
}

// ygemm cp role: 2560 pieces per tile (S 2048 + R 512), 10 per thread
__device__ __forceinline__ void yg_piece(int p, int c, int j0, int kb,
                                         const float*& src, unsigned& foff, int buf)
{
    if (p < 2048) {
        const int row = p >> 5, c16 = p & 31;
        src  = g_chk + ((size_t)c * DD + kb * GK + row) * DD + j0 + c16 * 4;
        foff = (unsigned)(YG_SS + buf * GK * GJ + row * GJ + c16 * 4);
    } else {
        const int q = p - 2048;
        const int t = q >> 4, k16 = q & 15;
        src  = g_rt + (size_t)(c * LCH + t) * DD + kb * GK + k16 * 4;
        foff = (unsigned)(YG_SR + buf * 32 * RPITCH + t * RPITCH + k16 * 4);
    }
}

// ---------------------------------------------------------------------------
// K5: Y[c*32+t][j] = r~_t . S_c[:,j] + sum_s A[t][s] V[s][j] + ruk_t V[t][j].
// Grid (4 col-blocks, NCH chunks), 256 thr, 2 CTA/SM. Thread: rows {tq,tq+16},
// cols cg*8..+8. S/R streamed via 2-deep cp.async tiles.
// ---------------------------------------------------------------------------
__global__ void __launch_bounds__(256, 2) wkv_ygemm(
    const float* __restrict__ v, float* __restrict__ y)
{
    extern __shared__ __align__(16) float sm[];
    const int tid = threadIdx.x;
    const int jb = blockIdx.x, c = blockIdx.y;
    const int j0 = jb * GJ;
    const int tq = tid & 15, cg = tid >> 4;
    const unsigned su = (unsigned)__cvta_generic_to_shared(sm);

    // load V tile, A, ruk (plain LDG)
    for (int i = tid; i < 32 * GJ / 4; i += 256) {
        const int row = i >> 5, c4 = (i & 31) * 4;
        *(float4*)&sm[YG_SV + row * GJ + c4] =
            *(const float4*)&v[(size_t)(c * LCH + row) * DD + j0 + c4];
    }
    for (int i = tid; i < 1024; i += 256) {
        const int row = i >> 5, s = i & 31;
        sm[YG_SA + row * 33 + s] = g_A[(size_t)c * 1024 + i];
    }
    if (tid < 32) sm[YG_RK + tid] = g_ruk[c * LCH + tid];

    // issue S/R tiles 0 and 1
    for (int kb = 0; kb < 2; kb++) {
#pragma unroll
        for (int j = 0; j < 10; j++) {
            const int p = tid + j * 256;
            if (p < 2560) {
                const float* src; unsigned foff;
                yg_piece(p, c, j0, kb, src, foff, kb);
                CP16(su + foff * 4u, src);
            }
        }
        CP_COMMIT();
    }

    ull a2[2][4];
#pragma unroll
    for (int h = 0; h < 2; h++)
#pragma unroll
        for (int j = 0; j < 4; j++) a2[h][j] = 0ull;

    for (int kb = 0; kb < 8; kb++) {
        CP_WAIT1();
        __syncthreads();
        const int buf = kb & 1;
        const float* Sb = sm + YG_SS + buf * GK * GJ;
        const float* Rb = sm + YG_SR + buf * 32 * RPITCH;
#pragma unroll 4
        for (int kk = 0; kk < GK; kk++) {
            const float r0 = Rb[tq * RPITCH + kk];
            const float r1 = Rb[(tq + 16) * RPITCH + kk];
            const ull r0p = pk2(r0, r0), r1p = pk2(r1, r1);
            const ull* sp = (const ull*)(Sb + kk * GJ + cg * 8);
            const ull sA0 = sp[0], sA1 = sp[1], sA2 = sp[2], sA3 = sp[3];
            a2[0][0] = f2fma(r0p, sA0, a2[0][0]);
            a2[0][1] = f2fma(r0p, sA1, a2[0][1]);
            a2[0][2] = f2fma(r0p, sA2, a2[0][2]);
            a2[0][3] = f2fma(r0p, sA3, a2[0][3]);
            a2[1][0] = f2fma(r1p, sA0, a2[1][0]);
            a2[1][1] = f2fma(r1p, sA1, a2[1][1]);
            a2[1][2] = f2fma(r1p, sA2, a2[1][2]);
            a2[1][3] = f2fma(r1p, sA3, a2[1][3]);
        }
        __syncthreads();
        if (kb + 2 < 8) {
#pragma unroll
            for (int j = 0; j < 10; j++) {
                const int p = tid + j * 256;
                if (p < 2560) {
                    const float* src; unsigned foff;
                    yg_piece(p, c, j0, kb + 2, src, foff, buf);
                    CP16(su + foff * 4u, src);
                }
            }
        }
        CP_COMMIT();
    }

    // phase 2: intra (A masked, full 32-loop) + ruk term, then store
#pragma unroll
    for (int h = 0; h < 2; h++) {
        const int t = tq + h * 16;
        {
            const float rk = sm[YG_RK + t];
            const ull rkp = pk2(rk, rk);
            const ull* vt = (const ull*)(sm + YG_SV + t * GJ + cg * 8);
#pragma unroll
            for (int j = 0; j < 4; j++) a2[h][j] = f2fma(rkp, vt[j], a2[h][j]);
        }
        for (int s = 0; s < 32; s++) {
            const float av = sm[YG_SA + t * 33 + s];
            const ull avp = pk2(av, av);
            const ull* vs = (const ull*)(sm + YG_SV + s * GJ + cg * 8);
#pragma unroll
            for (int j = 0; j < 4; j++) a2[h][j] = f2fma(avp, vs[j], a2[h][j]);
        }
        ull* yr = (ull*)(y + (size_t)(c * LCH + t) * DD + j0 + cg * 8);
#pragma unroll
        for (int j = 0; j < 4; j++) yr[j] = a2[h][j];
    }
}

// ---------------------------------------------------------------------------
extern "C" void kernel_launch(void* const* d_in, const int* in_sizes, int n_in,
                              void* d_out, int out_size) {
    const float* r          = (const float*)d_in[0];
    const float* w          = (const float*)d_in[1];
    const float* k          = (const float*)d_in[2];
    const float* v          = (const float*)d_in[3];
    const float* init_state = (const float*)d_in[4];
    const float* u          = (const float*)d_in[5];
    float* out = (float*)d_out;

    const int NTD = TT * DD;
    const int NDD = DD * DD;

    float* y  = nullptr;
    float* st = nullptr;
    if (out_size >= NTD) {
        y = out;
        if (out_size >= NTD + NDD) st = out + NTD;
    } else if (out_size == NDD) {
        st = out;
    }

    cudaFuncSetAttribute(wkv_ygemm, cudaFuncAttributeMaxDynamicSharedMemorySize, YG_SMEM);

    wkv_pre<<<dim3(NCH, 2), 256>>>(r, w, k);
    wkv_state<<<dim3(16, 8), 256>>>(v, init_state, st);
    if (y) {
        wkv_amat<<<NCH, 256>>>();
        wkv_ruk<<<TT / 8, 256>>>(r, k, u);
        wkv_ygemm<<<dim3(4, NCH), 256, YG_SMEM>>>(v, y);
    }
}

// round 12
// speedup vs baseline: 1.0530x; 1.0530x over previous
#include <cuda_runtime.h>
#include <cstdint>

#define TT 2048
#define DD 512
#define LCH 32
#define NCH (TT / LCH)            // 64
// state kernel staging
#define SSTEPS 32                 // one chunk per block
#define SSTEP_F 96                // k~64 + v32
#define SSTAGE_F (SSTEPS * SSTEP_F)   // 3072 floats
#define SSTAGE_B (SSTAGE_F * 4)       // 12288 B
#define SNSTG 3
// ygemm tiling
#define GJ 128                    // cols per CTA
#define GK 64                     // K rows per S tile
#define RPITCH 68                 // Rb row pitch (floats)
// ygemm smem offsets (floats)
#define YG_SS 0                           // [2][GK*GJ]     16384
#define YG_SR (YG_SS + 2 * GK * GJ)       // [2][32*RPITCH]  4352
#define YG_SV (YG_SR + 2 * 32 * RPITCH)   // [32*GJ]         4096
#define YG_SA (YG_SV + 32 * GJ)           // [32*33]         1056
#define YG_RK (YG_SA + 32 * 33)           // [32]
#define YG_FLOATS (YG_RK + 32)
#define YG_SMEM (YG_FLOATS * 4)           // 103680 B

// scratch (device globals — no allocation allowed)
__device__ float g_chk[(size_t)NCH * DD * DD];  // 64 MB chunk-start checkpoints
__device__ float g_rt[(size_t)TT * DD];         // r~ = r * P_prev
__device__ float g_kt[(size_t)TT * DD];         // k~ = k / P
__device__ float g_pl[(size_t)NCH * DD];        // per-chunk decay P_L
__device__ float g_A[(size_t)NCH * LCH * LCH];  // masked intra-chunk A
__device__ float g_ruk[TT];

typedef unsigned long long ull;

__device__ __forceinline__ ull pk2(float lo, float hi) {
    ull r; asm("mov.b64 %0,{%1,%2};" : "=l"(r) : "f"(lo), "f"(hi)); return r;
}
__device__ __forceinline__ void up2(ull x, float& lo, float& hi) {
    asm("mov.b64 {%0,%1},%2;" : "=f"(lo), "=f"(hi) : "l"(x));
}
__device__ __forceinline__ ull f2fma(ull a, ull b, ull c) {
    ull d; asm("fma.rn.f32x2 %0,%1,%2,%3;" : "=l"(d) : "l"(a), "l"(b), "l"(c)); return d;
}
__device__ __forceinline__ ull f2mul(ull a, ull b) {
    ull d; asm("mul.rn.f32x2 %0,%1,%2;" : "=l"(d) : "l"(a), "l"(b)); return d;
}
__device__ __forceinline__ ull f2add(ull a, ull b) {
    ull d; asm("add.rn.f32x2 %0,%1,%2;" : "=l"(d) : "l"(a), "l"(b)); return d;
}

#define CP16(dst, src) asm volatile("cp.async.cg.shared.global [%0], [%1], 16;\n" :: "r"(dst), "l"(src))
#define CP_COMMIT()    asm volatile("cp.async.commit_group;\n")
#define CP_WAIT1()     asm volatile("cp.async.wait_group 1;\n" ::: "memory")

// ---------------------------------------------------------------------------
// K1: per-chunk cumulative decay; emit r~, k~, P_L. grid (NCH, 2) x 256.
// ---------------------------------------------------------------------------
__global__ void __launch_bounds__(256) wkv_pre(
    const float* __restrict__ r, const float* __restrict__ w,
    const float* __restrict__ k)
{
    const int a = blockIdx.y * 256 + threadIdx.x;
    const int c = blockIdx.x;
    const size_t base = (size_t)c * LCH * DD + a;
    float P = 1.f;
#pragma unroll 4
    for (int s = 0; s < LCH; s++) {
        const size_t idx = base + (size_t)s * DD;
        const float rv = r[idx], wv = w[idx], kv = k[idx];
        g_rt[idx] = rv * P;
        P = fmaxf(P * wv, 1e-30f);
        g_kt[idx] = __fdividef(kv, P);
    }
    g_pl[(size_t)c * DD + a] = P;
}

// state-kernel cp role: 24 pieces per step, 768 per block, 3 per thread
__device__ __forceinline__ void cp_role_s(
    int piece, const float* v, int bx, int by,
    const float*& src, unsigned& foff)
{
    const int stp  = piece / 24;
    const int role = piece - stp * 24;
    if (role < 16) {
        src  = g_kt + by * 64 + role * 4;
        foff = (unsigned)(stp * SSTEP_F + role * 4);
    } else {
        const int q = role - 16;
        src  = v + bx * 32 + q * 4;
        foff = (unsigned)(stp * SSTEP_F + 64 + q * 4);
    }
    src += (size_t)stp * DD;
}

// ---------------------------------------------------------------------------
// K2 (sequential): state propagation ONLY. Grid (16,8), 256 thr, 1 CTA/SM.
// Per chunk: write checkpoint S_c, acc += k~*v over 32 steps, S = P_L*(S+acc).
// ---------------------------------------------------------------------------
__global__ void __launch_bounds__(256, 1) wkv_state(
    const float* __restrict__ v, const float* __restrict__ init_state,
    float* __restrict__ state_out)
{
    __shared__ __align__(16) float stage[SNSTG * SSTAGE_F];   // 36.9 KB

    const int tid  = threadIdx.x;
    const int bx   = blockIdx.x;
    const int by   = blockIdx.y;
    const int wid  = tid >> 5;
    const int lane = tid & 31;
    const int c    = lane & 3;
    const int rg   = lane >> 2;
    const int col32 = wid * 4 + c;
    const int b    = bx * 32 + col32;
    const int a0   = by * 64 + rg * 8;

    const unsigned su = (unsigned)__cvta_generic_to_shared(stage);

    const float *s0, *s1, *s2s;
    unsigned o0, o1, o2;
    cp_role_s(tid,       v, bx, by, s0, o0);
    cp_role_s(tid + 256, v, bx, by, s1, o1);
    cp_role_s(tid + 512, v, bx, by, s2s, o2);
    o0 = su + o0 * 4u; o1 = su + o1 * 4u; o2 = su + o2 * 4u;

    const float is0 = init_state[b];
    ull s2[4], acc[4];
    {
        ull iv = pk2(is0, is0);
#pragma unroll
        for (int i = 0; i < 4; i++) { s2[i] = iv; acc[i] = 0ull; }
    }

    // prologue: blocks 0,1
    CP16(o0, s0); CP16(o1, s1); CP16(o2, s2s); CP_COMMIT();
    s0 += SSTEPS * DD; s1 += SSTEPS * DD; s2s += SSTEPS * DD;
    CP16(o0 + SSTAGE_B, s0); CP16(o1 + SSTAGE_B, s1); CP16(o2 + SSTAGE_B, s2s); CP_COMMIT();
    s0 += SSTEPS * DD; s1 += SSTEPS * DD; s2s += SSTEPS * DD;
    CP_WAIT1();
    __syncthreads();

    int gOff = 0;
    unsigned giOff = 2 * SSTAGE_B;

    for (int blk = 0; blk < NCH; blk++) {
        // checkpoint: S at chunk start
        {
            float* chk = g_chk + (size_t)blk * DD * DD;
#pragma unroll
            for (int j = 0; j < 4; j++) {
                float lo, hi; up2(s2[j], lo, hi);
                chk[(size_t)(a0 + 2 * j)     * DD + b] = lo;
                chk[(size_t)(a0 + 2 * j + 1) * DD + b] = hi;
            }
        }
        // this chunk's P_L
        ull pl2[4];
        {
            const float4* plp = (const float4*)(g_pl + (size_t)blk * DD + a0);
            float4 pa = plp[0], pb = plp[1];
            pl2[0] = pk2(pa.x, pa.y); pl2[1] = pk2(pa.z, pa.w);
            pl2[2] = pk2(pb.x, pb.y); pl2[3] = pk2(pb.z, pb.w);
        }

        const char* sgb = (const char*)stage + gOff;
#pragma unroll
        for (int st = 0; st < SSTEPS; st++) {
            const ull* sb = (const ull*)(sgb + st * (SSTEP_F * 4));
            ulonglong2 ka = *reinterpret_cast<const ulonglong2*>(sb + rg * 4);
            ulonglong2 kb = *reinterpret_cast<const ulonglong2*>(sb + rg * 4 + 2);
            const float vf = ((const float*)sb)[64 + col32];
            const ull vv = pk2(vf, vf);
            acc[0] = f2fma(ka.x, vv, acc[0]);
            acc[1] = f2fma(ka.y, vv, acc[1]);
            acc[2] = f2fma(kb.x, vv, acc[2]);
            acc[3] = f2fma(kb.y, vv, acc[3]);
        }

        // chunk end: S = P_L * (S + acc)
#pragma unroll
        for (int i = 0; i < 4; i++) {
            s2[i] = f2mul(pl2[i], f2add(s2[i], acc[i]));
            acc[i] = 0ull;
        }

        // stage block blk+2
        if (blk + 2 < NCH) { CP16(o0 + giOff, s0); CP16(o1 + giOff, s1); CP16(o2 + giOff, s2s); }
        s0 += SSTEPS * DD; s1 += SSTEPS * DD; s2s += SSTEPS * DD;
        CP_COMMIT();
        CP_WAIT1();
        __syncthreads();

        gOff  = (gOff  == (SNSTG - 1) * SSTAGE_B) ? 0 : gOff  + SSTAGE_B;
        giOff = (giOff == (SNSTG - 1) * SSTAGE_B) ? 0 : giOff + SSTAGE_B;
    }

    if (state_out) {
#pragma unroll
        for (int j = 0; j < 4; j++) {
            float lo, hi; up2(s2[j], lo, hi);
            state_out[(size_t)(a0 + 2 * j)     * DD + b] = lo;
            state_out[(size_t)(a0 + 2 * j + 1) * DD + b] = hi;
        }
    }
}

// ---------------------------------------------------------------------------
// K3: A[c][t][s] = r~_t . k~_s (strict lower triangle, else 0). grid NCH.
// ---------------------------------------------------------------------------
__global__ void __launch_bounds__(256) wkv_amat()
{
    __shared__ float sR[32][68], sK[32][68];
    const int cc = blockIdx.x;
    const int tid = threadIdx.x;
    const int t = tid >> 3, sq = (tid & 7) * 4;
    float acc[4] = {0.f, 0.f, 0.f, 0.f};

    for (int kk = 0; kk < DD; kk += 64) {
        for (int i = tid; i < 32 * 16; i += 256) {
            const int row = i >> 4, col4 = (i & 15) * 4;
            const size_t gidx = (size_t)(cc * LCH + row) * DD + kk + col4;
            *(float4*)&sR[row][col4] = *(const float4*)&g_rt[gidx];
            *(float4*)&sK[row][col4] = *(const float4*)&g_kt[gidx];
        }
        __syncthreads();
        for (int j = 0; j < 64; j++) {
            const float rv = sR[t][j];
            acc[0] += rv * sK[sq + 0][j];
            acc[1] += rv * sK[sq + 1][j];
            acc[2] += rv * sK[sq + 2][j];
            acc[3] += rv * sK[sq + 3][j];
        }
        __syncthreads();
    }
#pragma unroll
    for (int i = 0; i < 4; i++)
        g_A[(size_t)(cc * LCH + t) * LCH + sq + i] = (sq + i < t) ? acc[i] : 0.f;
}

// ---------------------------------------------------------------------------
// K4: ruk_t = sum_a r*u*k. grid TT/8 x 256 (warp per t), float4-vectorized.
// ---------------------------------------------------------------------------
__global__ void __launch_bounds__(256) wkv_ruk(
    const float* __restrict__ r, const float* __restrict__ k,
    const float* __restrict__ u)
{
    const int wid = threadIdx.x >> 5, lane = threadIdx.x & 31;
    const int t = blockIdx.x * 8 + wid;
    const float* rt = r + (size_t)t * DD;
    const float* kt = k + (size_t)t * DD;
    float p = 0.f;
#pragma unroll
    for (int i = 0; i < 4; i++) {
        const int a = lane * 4 + i * 128;
        const float4 rv = *(const float4*)&rt[a];
        const float4 kv = *(const float4*)&kt[a];
        const float4 uv = *(const float4*)&u[a];
        p += rv.x * uv.x * kv.x + rv.y * uv.y * kv.y
           + rv.z * uv.z * kv.z + rv.w * uv.w * kv.w;
    }
#pragma unroll
    for (int m = 16; m >= 1; m >>= 1) p += __shfl_xor_sync(0xffffffffu, p, m);
    if (lane == 0) g_ruk[t] = p;
}

// ygemm cp pieces: 2560 per tile (S 2048 + R 512), 10 per thread
__device__ __forceinline__ void yg_piece(int p, int c, int j0, int kb,
                                         const float*& src, unsigned& foff, int buf)
{
    if (p < 2048) {
        const int row = p >> 5, c16 = p & 31;
        src  = g_chk + ((size_t)c * DD + kb * GK + row) * DD + j0 + c16 * 4;
        foff = (unsigned)(YG_SS + buf * GK * GJ + row * GJ + c16 * 4);
    } else {
        const int q = p - 2048;
        const int t = q >> 4, k16 = q & 15;
        src  = g_rt + (size_t)(c * LCH + t) * DD + kb * GK + k16 * 4;
        foff = (unsigned)(YG_SR + buf * 32 * RPITCH + t * RPITCH + k16 * 4);
    }
}

// ---------------------------------------------------------------------------
// K5: Y[c*32+t][j] = r~_t . S_c[:,j] + sum_s A[t][s] V[s][j] + ruk_t V[t][j].
// Grid (4, NCH), 256 thr, 2 CTA/SM. Thread: rows {tq, tq+16}, cols cg*8..+8.
// Inner loop: Rb via float4 (2 LDS.128 / 4kk), Sb via 2 LDS.128/kk.
// ---------------------------------------------------------------------------
__global__ void __launch_bounds__(256, 2) wkv_ygemm(
    const float* __restrict__ v, float* __restrict__ y)
{
    extern __shared__ __align__(16) float sm[];
    const int tid = threadIdx.x;
    const int jb = blockIdx.x, c = blockIdx.y;
    const int j0 = jb * GJ;
    const int tq = tid & 15, cg = tid >> 4;
    const unsigned su = (unsigned)__cvta_generic_to_shared(sm);

    // load V tile, A, ruk (plain LDG -> STS, covered by first sync)
    for (int i = tid; i < 32 * GJ / 4; i += 256) {
        const int row = i >> 5, c4 = (i & 31) * 4;
        *(float4*)&sm[YG_SV + row * GJ + c4] =
            *(const float4*)&v[(size_t)(c * LCH + row) * DD + j0 + c4];
    }
    for (int i = tid; i < 1024; i += 256) {
        const int row = i >> 5, s = i & 31;
        sm[YG_SA + row * 33 + s] = g_A[(size_t)c * 1024 + i];
    }
    if (tid < 32) sm[YG_RK + tid] = g_ruk[c * LCH + tid];

    // issue S/R tiles 0 and 1
    for (int kb = 0; kb < 2; kb++) {
#pragma unroll
        for (int j = 0; j < 10; j++) {
            const int p = tid + j * 256;
            if (p < 2560) {
                const float* src; unsigned foff;
                yg_piece(p, c, j0, kb, src, foff, kb);
                CP16(su + foff * 4u, src);
            }
        }
        CP_COMMIT();
    }

    ull a2[2][4];
#pragma unroll
    for (int h = 0; h < 2; h++)
#pragma unroll
        for (int j = 0; j < 4; j++) a2[h][j] = 0ull;

    for (int kb = 0; kb < 8; kb++) {
        CP_WAIT1();
        __syncthreads();
        const int buf = kb & 1;
        const float* Sb = sm + YG_SS + buf * GK * GJ;
        const float* Rb = sm + YG_SR + buf * 32 * RPITCH;

#pragma unroll 4
        for (int kk4 = 0; kk4 < GK / 4; kk4++) {
            const float4 r0v = *(const float4*)&Rb[tq * RPITCH + kk4 * 4];
            const float4 r1v = *(const float4*)&Rb[(tq + 16) * RPITCH + kk4 * 4];
#pragma unroll
            for (int q = 0; q < 4; q++) {
                const float r0 = (&r0v.x)[q];
                const float r1 = (&r1v.x)[q];
                const ull r0p = pk2(r0, r0), r1p = pk2(r1, r1);
                const ulonglong2* sp =
                    (const ulonglong2*)(Sb + (kk4 * 4 + q) * GJ + cg * 8);
                const ulonglong2 sA = sp[0], sB = sp[1];
                a2[0][0] = f2fma(r0p, sA.x, a2[0][0]);
                a2[0][1] = f2fma(r0p, sA.y, a2[0][1]);
                a2[0][2] = f2fma(r0p, sB.x, a2[0][2]);
                a2[0][3] = f2fma(r0p, sB.y, a2[0][3]);
                a2[1][0] = f2fma(r1p, sA.x, a2[1][0]);
                a2[1][1] = f2fma(r1p, sA.y, a2[1][1]);
                a2[1][2] = f2fma(r1p, sB.x, a2[1][2]);
                a2[1][3] = f2fma(r1p, sB.y, a2[1][3]);
            }
        }
        __syncthreads();
        if (kb + 2 < 8) {
#pragma unroll
            for (int j = 0; j < 10; j++) {
                const int p = tid + j * 256;
                if (p < 2560) {
                    const float* src; unsigned foff;
                    yg_piece(p, c, j0, kb + 2, src, foff, buf);
                    CP16(su + foff * 4u, src);
                }
            }
        }
        CP_COMMIT();
    }

    // epilogue: ruk term + A.V (V loads shared across both output rows)
    {
        const float rk0 = sm[YG_RK + tq];
        const float rk1 = sm[YG_RK + tq + 16];
        const ull rk0p = pk2(rk0, rk0), rk1p = pk2(rk1, rk1);
        {
            const ulonglong2* vt0 = (const ulonglong2*)(sm + YG_SV + tq * GJ + cg * 8);
            const ulonglong2 tA = vt0[0], tB = vt0[1];
            a2[0][0] = f2fma(rk0p, tA.x, a2[0][0]);
            a2[0][1] = f2fma(rk0p, tA.y, a2[0][1]);
            a2[0][2] = f2fma(rk0p, tB.x, a2[0][2]);
            a2[0][3] = f2fma(rk0p, tB.y, a2[0][3]);
        }
        {
            const ulonglong2* vt1 = (const ulonglong2*)(sm + YG_SV + (tq + 16) * GJ + cg * 8);
            const ulonglong2 tA = vt1[0], tB = vt1[1];
            a2[1][0] = f2fma(rk1p, tA.x, a2[1][0]);
            a2[1][1] = f2fma(rk1p, tA.y, a2[1][1]);
            a2[1][2] = f2fma(rk1p, tB.x, a2[1][2]);
            a2[1][3] = f2fma(rk1p, tB.y, a2[1][3]);
        }
        for (int s = 0; s < 32; s++) {
            const float av0 = sm[YG_SA + tq * 33 + s];
            const float av1 = sm[YG_SA + (tq + 16) * 33 + s];
            const ull av0p = pk2(av0, av0), av1p = pk2(av1, av1);
            const ulonglong2* vs = (const ulonglong2*)(sm + YG_SV + s * GJ + cg * 8);
            const ulonglong2 sA = vs[0], sB = vs[1];
            a2[0][0] = f2fma(av0p, sA.x, a2[0][0]);
            a2[0][1] = f2fma(av0p, sA.y, a2[0][1]);
            a2[0][2] = f2fma(av0p, sB.x, a2[0][2]);
            a2[0][3] = f2fma(av0p, sB.y, a2[0][3]);
            a2[1][0] = f2fma(av1p, sA.x, a2[1][0]);
            a2[1][1] = f2fma(av1p, sA.y, a2[1][1]);
            a2[1][2] = f2fma(av1p, sB.x, a2[1][2]);
            a2[1][3] = f2fma(av1p, sB.y, a2[1][3]);
        }
    }
#pragma unroll
    for (int h = 0; h < 2; h++) {
        const int t = tq + h * 16;
        ull* yr = (ull*)(y + (size_t)(c * LCH + t) * DD + j0 + cg * 8);
#pragma unroll
        for (int j = 0; j < 4; j++) yr[j] = a2[h][j];
    }
}

// ---------------------------------------------------------------------------
extern "C" void kernel_launch(void* const* d_in, const int* in_sizes, int n_in,
                              void* d_out, int out_size) {
    const float* r          = (const float*)d_in[0];
    const float* w          = (const float*)d_in[1];
    const float* k          = (const float*)d_in[2];
    const float* v          = (const float*)d_in[3];
    const float* init_state = (const float*)d_in[4];
    const float* u          = (const float*)d_in[5];
    float* out = (float*)d_out;

    const int NTD = TT * DD;
    const int NDD = DD * DD;

    float* y  = nullptr;
    float* st = nullptr;
    if (out_size >= NTD) {
        y = out;
        if (out_size >= NTD + NDD) st = out + NTD;
    } else if (out_size == NDD) {
        st = out;
    }

    cudaFuncSetAttribute(wkv_ygemm, cudaFuncAttributeMaxDynamicSharedMemorySize, YG_SMEM);

    wkv_pre<<<dim3(NCH, 2), 256>>>(r, w, k);
    wkv_state<<<dim3(16, 8), 256>>>(v, init_state, st);
    if (y) {
        wkv_amat<<<NCH, 256>>>();
        wkv_ruk<<<TT / 8, 256>>>(r, k, u);
        wkv_ygemm<<<dim3(4, NCH), 256, YG_SMEM>>>(v, y);
    }
}

// round 14
// speedup vs baseline: 1.1711x; 1.1121x over previous
#include <cuda_runtime.h>
#include <cstdint>

#define TT 2048
#define DD 512
#define STEPS 16
#define NBLK (TT / STEPS)         // 128
#define NSTG 4
#define STEP_F 224                // floats per step staged: r64 w64 k64 v32
#define STAGE_F (STEPS * STEP_F)  // 3584 floats per stage buffer
#define STAGE_B (STAGE_F * 4)     // 14336 bytes
#define PART_F (2 * STEPS * 16 * 32)   // [parity][st][rg][col] = 16384 floats
#define SMEM_FLOATS (NSTG * STAGE_F + PART_F)   // 30720 floats = 120 KB

// 8 row-blocks of partial y sums, [8][T][D] = 32 MB scratch (deterministic)
__device__ float g_part[(size_t)8 * TT * DD];

typedef unsigned long long ull;

__device__ __forceinline__ ull pk2(float lo, float hi) {
    ull r; asm("mov.b64 %0,{%1,%2};" : "=l"(r) : "f"(lo), "f"(hi)); return r;
}
__device__ __forceinline__ void up2(ull x, float& lo, float& hi) {
    asm("mov.b64 {%0,%1},%2;" : "=f"(lo), "=f"(hi) : "l"(x));
}
__device__ __forceinline__ ull f2fma(ull a, ull b, ull c) {
    ull d; asm("fma.rn.f32x2 %0,%1,%2,%3;" : "=l"(d) : "l"(a), "l"(b), "l"(c)); return d;
}
__device__ __forceinline__ ull f2mul(ull a, ull b) {
    ull d; asm("mul.rn.f32x2 %0,%1,%2;" : "=l"(d) : "l"(a), "l"(b)); return d;
}

#define CP16(dst, src) asm volatile("cp.async.cg.shared.global [%0], [%1], 16;\n" :: "r"(dst), "l"(src))
#define CP_COMMIT()    asm volatile("cp.async.commit_group;\n")
#define CP_WAIT2()     asm volatile("cp.async.wait_group 2;\n" ::: "memory")

// role -> (gmem base pointer, float offset within one step's stage slot)
__device__ __forceinline__ void cp_role(
    int piece, const float* r, const float* w, const float* k, const float* v,
    int bx, int by, const float*& src, unsigned& foff)
{
    const int stp  = piece / 56;          // step within block (0..15)
    const int role = piece - stp * 56;    // 0..55
    const float* basep; int off;
    if (role < 48) {
        const int vec = role >> 4;        // 0=r 1=w 2=k
        basep = ((vec == 0) ? r : (vec == 1) ? w : k) + by * 64 + (role & 15) * 4;
        off = vec * 64 + (role & 15) * 4;
    } else {
        const int q = role - 48;
        basep = v + bx * 32 + q * 4;
        off = 192 + q * 4;
    }
    src  = basep + (size_t)stp * DD;
    foff = (unsigned)(stp * STEP_F + off);
}

// ---------------------------------------------------------------------------
// Main recurrence kernel. Grid (16 col-blocks, 8 row-blocks), 512 threads,
// 1 CTA/SM => 4 warps/SMSP. CTA tile 64 rows x 32 cols.
// Warp wid (0..15) = row-group wid (4 rows), all 32 cols; lane = col.
// Thread: 4 rows x 1 col as 2 f32x2 pairs. Stage loads are warp-broadcast
// LDS.128 (r/w/k) + coalesced LDS.32 (v). 16 steps per block: ONE barrier +
// ONE cp wait + ONE batched conflict-free reduction. 4-deep cp.async ring.
// ---------------------------------------------------------------------------
__global__ void __launch_bounds__(512, 1) wkv_main(
    const float* __restrict__ r, const float* __restrict__ w,
    const float* __restrict__ k, const float* __restrict__ v,
    const float* __restrict__ init_state, float* __restrict__ state_out)
{
    extern __shared__ __align__(16) float smem[];
    float* stage = smem;                       // [NSTG][STAGE_F]
    float* partb = smem + NSTG * STAGE_F;      // [2][16 st][16 rg][32 col]

    const int tid  = threadIdx.x;
    const int bx   = blockIdx.x;
    const int by   = blockIdx.y;
    const int wid  = tid >> 5;                 // row group (0..15), 4 rows
    const int lane = tid & 31;                 // col within tile
    const int b    = bx * 32 + lane;           // global column
    const int a0   = by * 64 + wid * 4;        // first global row

    const unsigned smem_u32 = (unsigned)__cvta_generic_to_shared(smem);

    // ---- cp.async roles: 896 16B pieces per block; thread owns 1 or 2
    const bool has2 = (tid < 384);
    const float *s0, *s1;
    unsigned o0, o1;
    cp_role(tid, r, w, k, v, bx, by, s0, o0);
    cp_role(has2 ? tid + 512 : tid, r, w, k, v, bx, by, s1, o1);
    o0 = smem_u32 + o0 * 4u;
    o1 = smem_u32 + o1 * 4u;

    // ---- init state: state0[a][b] = init_state[b]
    const float is0 = init_state[b];
    ull s2[2];
    {
        ull iv = pk2(is0, is0);
        s2[0] = iv; s2[1] = iv;
    }

    // ---- prologue: stage blocks 0,1,2
#pragma unroll
    for (int s = 0; s < 3; s++) {
        const size_t adv = (size_t)s * STEPS * DD;
        const unsigned bo = s * STAGE_B;
        CP16(o0 + bo, s0 + adv);
        if (has2) CP16(o1 + bo, s1 + adv);
        CP_COMMIT();
    }
    s0 += (size_t)3 * STEPS * DD;
    s1 += (size_t)3 * STEPS * DD;
    CP_WAIT2();
    __syncthreads();

    // partial layout: partb[p][st][rg][col], pitch 32 (both R/W conflict-free)
    const int wbase = wid * 32 + lane;          // writer: + st*512 (+ parity)
    const int rst   = wid;                      // reader: st = wid, col = lane
    float* gpr = g_part + (size_t)by * TT * DD + (size_t)bx * 32 + lane;
    const int vidx = 192 + lane;

    int gOff  = 0;                  // byte offset of compute buffer
    unsigned giOff = 3 * STAGE_B;   // byte offset of next issue buffer

    for (int blk = 0; blk < NBLK; blk++) {
        const int p = blk & 1;
        const char* sgb = (const char*)stage + gOff;
        float* pp = partb + p * (STEPS * 16 * 32);
        float vals[STEPS];

#pragma unroll
        for (int st = 0; st < STEPS; st++) {
            const ull* sb = (const ull*)(sgb + st * (STEP_F * 4));

            // warp-broadcast 16B loads: rows 4*wid..4*wid+3 of r/w/k
            ulonglong2 ra = *reinterpret_cast<const ulonglong2*>(sb + wid * 2);
            ulonglong2 wa = *reinterpret_cast<const ulonglong2*>(sb + 32 + wid * 2);
            ulonglong2 ka = *reinterpret_cast<const ulonglong2*>(sb + 64 + wid * 2);
            const float vf = ((const float*)sb)[vidx];
            const ull vv = pk2(vf, vf);

            // y partial over this thread's 4 rows
            ull p2;
            p2 = f2mul(ra.x, s2[0]);
            p2 = f2fma(ra.y, s2[1], p2);

            // state update: s = w*s + k*v
            s2[0] = f2fma(wa.x, s2[0], f2mul(ka.x, vv));
            s2[1] = f2fma(wa.y, s2[1], f2mul(ka.y, vv));

            float pl, ph; up2(p2, pl, ph);
            vals[st] = pl + ph;
        }

        // batched partial write: 16 STS.32, coalesced (cols consecutive)
#pragma unroll
        for (int st = 0; st < STEPS; st++) pp[st * 512 + wbase] = vals[st];

        // stage block blk+3
        if (blk + 3 < NBLK) {
            CP16(o0 + giOff, s0);
            if (has2) CP16(o1 + giOff, s1);
        }
        s0 += STEPS * DD;
        s1 += STEPS * DD;
        CP_COMMIT();
        CP_WAIT2();
        __syncthreads();

        // batched reduction: thread (st = wid, col = lane) sums 16 rg
        // partials; conflict-free reads, coalesced 128B g_part store.
        {
            const float* pr = pp + rst * 512 + lane;
            float acc = pr[0];
#pragma unroll
            for (int g = 1; g < 16; g++) acc += pr[g * 32];
            gpr[(size_t)(blk * STEPS + rst) * DD] = acc;
        }

        gOff  = (gOff  == (NSTG - 1) * STAGE_B) ? 0 : gOff  + STAGE_B;
        giOff = (giOff == (NSTG - 1) * STAGE_B) ? 0 : giOff + STAGE_B;
    }

    // ---- final state write (4 rows x 1 col per thread)
    if (state_out) {
#pragma unroll
        for (int i = 0; i < 2; i++) {
            float lo, hi; up2(s2[i], lo, hi);
            state_out[(size_t)(a0 + 2 * i)     * DD + b] = lo;
            state_out[(size_t)(a0 + 2 * i + 1) * DD + b] = hi;
        }
    }
}

// ---------------------------------------------------------------------------
// Combine: y[t][b] = (sum_a r*u*k)*v[t][b] + sum of 8 row-block partials.
// ---------------------------------------------------------------------------
__global__ void __launch_bounds__(256) wkv_combine(
    const float* __restrict__ r, const float* __restrict__ k,
    const float* __restrict__ u, const float* __restrict__ v,
    float* __restrict__ y)
{
    const int t = blockIdx.x;
    const int tid = threadIdx.x;
    __shared__ float red[8];

    const float* rt = r + (size_t)t * DD;
    const float* kt = k + (size_t)t * DD;

    float p = rt[tid] * u[tid] * kt[tid]
            + rt[tid + 256] * u[tid + 256] * kt[tid + 256];
#pragma unroll
    for (int m = 16; m >= 1; m >>= 1) p += __shfl_xor_sync(0xffffffffu, p, m);
    if ((tid & 31) == 0) red[tid >> 5] = p;
    __syncthreads();

    float ruk = 0.f;
#pragma unroll
    for (int g = 0; g < 8; g++) ruk += red[g];

    const float2* v2 = (const float2*)(v + (size_t)t * DD);
    float2* y2 = (float2*)(y + (size_t)t * DD);
    float2 vv = v2[tid];
    float2 acc; acc.x = ruk * vv.x; acc.y = ruk * vv.y;
#pragma unroll
    for (int g = 0; g < 8; g++) {
        const float2* gp2 = (const float2*)(g_part + (size_t)g * TT * DD + (size_t)t * DD);
        float2 pv = gp2[tid];
        acc.x += pv.x; acc.y += pv.y;
    }
    y2[tid] = acc;
}

// ---------------------------------------------------------------------------
extern "C" void kernel_launch(void* const* d_in, const int* in_sizes, int n_in,
                              void* d_out, int out_size) {
    const float* r          = (const float*)d_in[0];
    const float* w          = (const float*)d_in[1];
    const float* k          = (const float*)d_in[2];
    const float* v          = (const float*)d_in[3];
    const float* init_state = (const float*)d_in[4];
    const float* u          = (const float*)d_in[5];
    float* out = (float*)d_out;

    const int NTD = TT * DD;   // 1048576
    const int NDD = DD * DD;   // 262144

    float* y  = nullptr;
    float* st = nullptr;
    if (out_size >= NTD) {
        y = out;
        if (out_size >= NTD + NDD) st = out + NTD;
    } else if (out_size == NDD) {
        st = out;
    }

    const int smem_bytes = SMEM_FLOATS * 4;    // 122880
    cudaFuncSetAttribute(wkv_main, cudaFuncAttributeMaxDynamicSharedMemorySize, smem_bytes);

    wkv_main<<<dim3(16, 8), 512, smem_bytes>>>(r, w, k, v, init_state, st);
    if (y) wkv_combine<<<TT, 256>>>(r, k, u, v, y);
}

// round 15
// speedup vs baseline: 1.4310x; 1.2220x over previous
#include <cuda_runtime.h>
#include <cstdint>

#define TT 2048
#define DD 512
#define STEPS 32
#define NBLK (TT / STEPS)         // 64
#define NSTG 3
#define STEP_F 224                // floats per step staged: r64 w64 k64 v32
#define STAGE_F (STEPS * STEP_F)  // 7168 floats per stage buffer
#define STAGE_B (STAGE_F * 4)     // 28672 bytes
#define PART_HALF (STEPS * 8 * 36)          // 9216 floats per parity buffer
#define SMEM_FLOATS (NSTG * STAGE_F + 2 * PART_HALF)  // 39936 floats = 156 KB

// 8 row-blocks of partial y sums, [8][T][D] = 32 MB scratch (deterministic)
__device__ float g_part[(size_t)8 * TT * DD];

typedef unsigned long long ull;

__device__ __forceinline__ ull pk2(float lo, float hi) {
    ull r; asm("mov.b64 %0,{%1,%2};" : "=l"(r) : "f"(lo), "f"(hi)); return r;
}
__device__ __forceinline__ void up2(ull x, float& lo, float& hi) {
    asm("mov.b64 {%0,%1},%2;" : "=f"(lo), "=f"(hi) : "l"(x));
}
__device__ __forceinline__ ull f2fma(ull a, ull b, ull c) {
    ull d; asm("fma.rn.f32x2 %0,%1,%2,%3;" : "=l"(d) : "l"(a), "l"(b), "l"(c)); return d;
}
__device__ __forceinline__ ull f2mul(ull a, ull b) {
    ull d; asm("mul.rn.f32x2 %0,%1,%2;" : "=l"(d) : "l"(a), "l"(b)); return d;
}

#define CP16(dst, src) asm volatile("cp.async.cg.shared.global [%0], [%1], 16;\n" :: "r"(dst), "l"(src))
#define CP_COMMIT()    asm volatile("cp.async.commit_group;\n")
#define CP_WAIT1()     asm volatile("cp.async.wait_group 1;\n" ::: "memory")

// role -> (gmem base pointer, float offset within one step's stage slot)
// 56 roles per step x 32 steps = 1792 pieces per block; 7 per thread.
__device__ __forceinline__ void cp_role(
    int piece, const float* r, const float* w, const float* k, const float* v,
    int bx, int by, const float*& src, unsigned& foff)
{
    const int stp  = piece / 56;          // step within block (0..31)
    const int role = piece - stp * 56;    // 0..55
    const float* basep; int off;
    if (role < 48) {
        const int vec = role >> 4;        // 0=r 1=w 2=k
        basep = ((vec == 0) ? r : (vec == 1) ? w : k) + by * 64 + (role & 15) * 4;
        off = vec * 64 + (role & 15) * 4;
    } else {
        const int q = role - 48;
        basep = v + bx * 32 + q * 4;
        off = 192 + q * 4;
    }
    src  = basep + (size_t)stp * DD;
    foff = (unsigned)(stp * STEP_F + off);
}

// ---------------------------------------------------------------------------
// Main recurrence kernel. Grid (16 col-blocks, 8 row-blocks), 256 threads,
// 1 CTA/SM. CTA tile 64 rows x 32 cols; warp wid owns cols [wid*4,wid*4+4),
// lane = rg*4 + c; thread = 8 rows x 1 col as 4 f32x2 pairs.
// 32 steps per block: ONE barrier + ONE cp wait + ONE batched reduction.
// 3-deep cp.async ring (wait_group 1 => 1 full block of slack; issue blk+2).
// ---------------------------------------------------------------------------
__global__ void __launch_bounds__(256, 1) wkv_main(
    const float* __restrict__ r, const float* __restrict__ w,
    const float* __restrict__ k, const float* __restrict__ v,
    const float* __restrict__ init_state, float* __restrict__ state_out)
{
    extern __shared__ __align__(16) float smem[];
    float* stage = smem;                       // [NSTG][STAGE_F]
    float* partb = smem + NSTG * STAGE_F;      // [2][st][rg][36]

    const int tid  = threadIdx.x;
    const int bx   = blockIdx.x;
    const int by   = blockIdx.y;
    const int wid  = tid >> 5;
    const int lane = tid & 31;
    const int c    = lane & 3;
    const int rg   = lane >> 2;
    const int col32 = wid * 4 + c;
    const int b    = bx * 32 + col32;
    const int a0   = by * 64 + rg * 8;

    const unsigned smem_u32 = (unsigned)__cvta_generic_to_shared(smem);

    // ---- cp.async roles: 1792 pieces per block, exactly 7 per thread
    const float* srcs[7];
    unsigned offs[7];
#pragma unroll
    for (int j = 0; j < 7; j++) {
        cp_role(tid + j * 256, r, w, k, v, bx, by, srcs[j], offs[j]);
        offs[j] = smem_u32 + offs[j] * 4u;
    }

    // ---- init state: state0[a][b] = init_state[b]
    const float is0 = init_state[b];
    ull s2[4];
    {
        ull iv = pk2(is0, is0);
#pragma unroll
        for (int i = 0; i < 4; i++) s2[i] = iv;
    }

    // ---- prologue: stage blocks 0,1
#pragma unroll
    for (int s = 0; s < 2; s++) {
        const size_t adv = (size_t)s * STEPS * DD;
        const unsigned bo = s * STAGE_B;
#pragma unroll
        for (int j = 0; j < 7; j++) CP16(offs[j] + bo, srcs[j] + adv);
        CP_COMMIT();
    }
#pragma unroll
    for (int j = 0; j < 7; j++) srcs[j] += (size_t)2 * STEPS * DD;
    CP_WAIT1();
    __syncthreads();

    // partial roles: writer (rg,col32) -> pp[st*288 + rg*36 + col32]
    // banks 4(rg+wid)+c mod 32 distinct within warp -> conflict-free
    const int wbase = rg * 36 + col32;
    float* gpr = g_part + (size_t)by * TT * DD + (size_t)bx * 32 + lane;
    const int vidx = 192 + col32;

    int gOff  = 0;                  // byte offset of compute buffer
    unsigned giOff = 2 * STAGE_B;   // byte offset of next issue buffer

    for (int blk = 0; blk < NBLK; blk++) {
        const int p = blk & 1;
        const char* sgb = (const char*)stage + gOff;
        float* pp = partb + p * PART_HALF;

#pragma unroll
        for (int st = 0; st < STEPS; st++) {
            const ull* sb = (const ull*)(sgb + st * (STEP_F * 4));

            ulonglong2 ra = *reinterpret_cast<const ulonglong2*>(sb + rg * 4);
            ulonglong2 rb = *reinterpret_cast<const ulonglong2*>(sb + rg * 4 + 2);
            ulonglong2 wa = *reinterpret_cast<const ulonglong2*>(sb + 32 + rg * 4);
            ulonglong2 wb = *reinterpret_cast<const ulonglong2*>(sb + 32 + rg * 4 + 2);
            ulonglong2 ka = *reinterpret_cast<const ulonglong2*>(sb + 64 + rg * 4);
            ulonglong2 kb = *reinterpret_cast<const ulonglong2*>(sb + 64 + rg * 4 + 2);
            const float vf = ((const float*)sb)[vidx];
            const ull vv = pk2(vf, vf);

            // y partial = sum over this thread's 8 rows of r[a]*state[a][b]
            ull p2;
            p2 = f2mul(ra.x, s2[0]);
            p2 = f2fma(ra.y, s2[1], p2);
            p2 = f2fma(rb.x, s2[2], p2);
            p2 = f2fma(rb.y, s2[3], p2);

            // state update: s = w*s + k*v
            s2[0] = f2fma(wa.x, s2[0], f2mul(ka.x, vv));
            s2[1] = f2fma(wa.y, s2[1], f2mul(ka.y, vv));
            s2[2] = f2fma(wb.x, s2[2], f2mul(kb.x, vv));
            s2[3] = f2fma(wb.y, s2[3], f2mul(kb.y, vv));

            float pl, ph; up2(p2, pl, ph);
            pp[st * 288 + wbase] = pl + ph;   // inline STS, conflict-free
        }

        // stage block blk+2
        if (blk + 2 < NBLK) {
#pragma unroll
            for (int j = 0; j < 7; j++) CP16(offs[j] + giOff, srcs[j]);
        }
#pragma unroll
        for (int j = 0; j < 7; j++) srcs[j] += STEPS * DD;
        CP_COMMIT();
        CP_WAIT1();
        __syncthreads();

        // batched reduction: thread handles (col=lane, st = wid + 8h), h=0..3
        {
            const size_t t0 = (size_t)blk * STEPS;
#pragma unroll
            for (int h = 0; h < 4; h++) {
                const int st = wid + h * 8;
                const float* pr = pp + st * 288 + lane;
                float acc = pr[0];
#pragma unroll
                for (int g = 1; g < 8; g++) acc += pr[g * 36];
                gpr[(t0 + st) * DD] = acc;
            }
        }

        gOff  = (gOff  == (NSTG - 1) * STAGE_B) ? 0 : gOff  + STAGE_B;
        giOff = (giOff == (NSTG - 1) * STAGE_B) ? 0 : giOff + STAGE_B;
    }

    // ---- final state write
    if (state_out) {
#pragma unroll
        for (int i = 0; i < 4; i++) {
            float lo, hi; up2(s2[i], lo, hi);
            state_out[(size_t)(a0 + 2 * i)     * DD + b] = lo;
            state_out[(size_t)(a0 + 2 * i + 1) * DD + b] = hi;
        }
    }
}

// ---------------------------------------------------------------------------
// Combine: y[t][b] = (sum_a r*u*k)*v[t][b] + sum of 8 row-block partials.
// ---------------------------------------------------------------------------
__global__ void __launch_bounds__(256) wkv_combine(
    const float* __restrict__ r, const float* __restrict__ k,
    const float* __restrict__ u, const float* __restrict__ v,
    float* __restrict__ y)
{
    const int t = blockIdx.x;
    const int tid = threadIdx.x;
    __shared__ float red[8];

    const float* rt = r + (size_t)t * DD;
    const float* kt = k + (size_t)t * DD;

    float p = rt[tid] * u[tid] * kt[tid]
            + rt[tid + 256] * u[tid + 256] * kt[tid + 256];
#pragma unroll
    for (int m = 16; m >= 1; m >>= 1) p += __shfl_xor_sync(0xffffffffu, p, m);
    if ((tid & 31) == 0) red[tid >> 5] = p;
    __syncthreads();

    float ruk = 0.f;
#pragma unroll
    for (int g = 0; g < 8; g++) ruk += red[g];

    const float2* v2 = (const float2*)(v + (size_t)t * DD);
    float2* y2 = (float2*)(y + (size_t)t * DD);
    float2 vv = v2[tid];
    float2 acc; acc.x = ruk * vv.x; acc.y = ruk * vv.y;
#pragma unroll
    for (int g = 0; g < 8; g++) {
        const float2* gp2 = (const float2*)(g_part + (size_t)g * TT * DD + (size_t)t * DD);
        float2 pv = gp2[tid];
        acc.x += pv.x; acc.y += pv.y;
    }
    y2[tid] = acc;
}

// ---------------------------------------------------------------------------
extern "C" void kernel_launch(void* const* d_in, const int* in_sizes, int n_in,
                              void* d_out, int out_size) {
    const float* r          = (const float*)d_in[0];
    const float* w          = (const float*)d_in[1];
    const float* k          = (const float*)d_in[2];
    const float* v          = (const float*)d_in[3];
    const float* init_state = (const float*)d_in[4];
    const float* u          = (const float*)d_in[5];
    float* out = (float*)d_out;

    const int NTD = TT * DD;   // 1048576
    const int NDD = DD * DD;   // 262144

    float* y  = nullptr;
    float* st = nullptr;
    if (out_size >= NTD) {
        y = out;
        if (out_size >= NTD + NDD) st = out + NTD;
    } else if (out_size == NDD) {
        st = out;
    }

    const int smem_bytes = SMEM_FLOATS * 4;    // 159744
    cudaFuncSetAttribute(wkv_main, cudaFuncAttributeMaxDynamicSharedMemorySize, smem_bytes);

    wkv_main<<<dim3(16, 8), 256, smem_bytes>>>(r, w, k, v, init_state, st);
    if (y) wkv_combine<<<TT, 256>>>(r, k, u, v, y);
}

// round 16
// speedup vs baseline: 1.4317x; 1.0004x over previous
#include <cuda_runtime.h>
#include <cstdint>

#define TT 2048
#define DD 512
#define STEPS 32
#define NBLK (TT / STEPS)         // 64
#define NSTG 3
#define STEP_F 224                // floats per step staged: r64 w64 k64 v32
#define STAGE_F (STEPS * STEP_F)  // 7168 floats per stage buffer
#define STAGE_B (STAGE_F * 4)     // 28672 bytes
#define PART_HALF (STEPS * 8 * 36)          // 9216 floats per parity buffer
#define SMEM_FLOATS (NSTG * STAGE_F + 2 * PART_HALF)  // 39936 floats = 156 KB

// 8 row-blocks of partial y sums, [8][T][D] = 32 MB scratch (deterministic)
__device__ float g_part[(size_t)8 * TT * DD];

typedef unsigned long long ull;

__device__ __forceinline__ ull pk2(float lo, float hi) {
    ull r; asm("mov.b64 %0,{%1,%2};" : "=l"(r) : "f"(lo), "f"(hi)); return r;
}
__device__ __forceinline__ void up2(ull x, float& lo, float& hi) {
    asm("mov.b64 {%0,%1},%2;" : "=f"(lo), "=f"(hi) : "l"(x));
}
__device__ __forceinline__ ull f2fma(ull a, ull b, ull c) {
    ull d; asm("fma.rn.f32x2 %0,%1,%2,%3;" : "=l"(d) : "l"(a), "l"(b), "l"(c)); return d;
}
__device__ __forceinline__ ull f2mul(ull a, ull b) {
    ull d; asm("mul.rn.f32x2 %0,%1,%2;" : "=l"(d) : "l"(a), "l"(b)); return d;
}

#define CP16(dst, src) asm volatile("cp.async.cg.shared.global [%0], [%1], 16;\n" :: "r"(dst), "l"(src))
#define CP_COMMIT()    asm volatile("cp.async.commit_group;\n")
#define CP_WAIT1()     asm volatile("cp.async.wait_group 1;\n" ::: "memory")

// one step's operands, held in registers one step ahead of use
struct StepOps {
    ulonglong2 ra, rb, wa, wb, ka, kb;
    float vf;
};

__device__ __forceinline__ StepOps load_step(const ull* sb, int rg4, int vidx) {
    StepOps o;
    o.ra = *reinterpret_cast<const ulonglong2*>(sb + rg4);
    o.rb = *reinterpret_cast<const ulonglong2*>(sb + rg4 + 2);
    o.wa = *reinterpret_cast<const ulonglong2*>(sb + 32 + rg4);
    o.wb = *reinterpret_cast<const ulonglong2*>(sb + 32 + rg4 + 2);
    o.ka = *reinterpret_cast<const ulonglong2*>(sb + 64 + rg4);
    o.kb = *reinterpret_cast<const ulonglong2*>(sb + 64 + rg4 + 2);
    o.vf = reinterpret_cast<const float*>(sb)[vidx];
    return o;
}

// FMA order identical to R15 (bit-identical results)
__device__ __forceinline__ float do_step(const StepOps& o, ull s2[4]) {
    const ull vv = pk2(o.vf, o.vf);
    ull p2;
    p2 = f2mul(o.ra.x, s2[0]);
    p2 = f2fma(o.ra.y, s2[1], p2);
    p2 = f2fma(o.rb.x, s2[2], p2);
    p2 = f2fma(o.rb.y, s2[3], p2);
    s2[0] = f2fma(o.wa.x, s2[0], f2mul(o.ka.x, vv));
    s2[1] = f2fma(o.wa.y, s2[1], f2mul(o.ka.y, vv));
    s2[2] = f2fma(o.wb.x, s2[2], f2mul(o.kb.x, vv));
    s2[3] = f2fma(o.wb.y, s2[3], f2mul(o.kb.y, vv));
    float pl, ph; up2(p2, pl, ph);
    return pl + ph;
}

// role -> (gmem base pointer, float offset within one step's stage slot)
// 56 roles per step x 32 steps = 1792 pieces per block; 7 per thread.
__device__ __forceinline__ void cp_role(
    int piece, const float* r, const float* w, const float* k, const float* v,
    int bx, int by, const float*& src, unsigned& foff)
{
    const int stp  = piece / 56;          // step within block (0..31)
    const int role = piece - stp * 56;    // 0..55
    const float* basep; int off;
    if (role < 48) {
        const int vec = role >> 4;        // 0=r 1=w 2=k
        basep = ((vec == 0) ? r : (vec == 1) ? w : k) + by * 64 + (role & 15) * 4;
        off = vec * 64 + (role & 15) * 4;
    } else {
        const int q = role - 48;
        basep = v + bx * 32 + q * 4;
        off = 192 + q * 4;
    }
    src  = basep + (size_t)stp * DD;
    foff = (unsigned)(stp * STEP_F + off);
}

// ---------------------------------------------------------------------------
// Main recurrence kernel. Grid (16 col-blocks, 8 row-blocks), 256 threads,
// 1 CTA/SM. CTA tile 64 rows x 32 cols; warp wid owns cols [wid*4,wid*4+4),
// lane = rg*4 + c; thread = 8 rows x 1 col as 4 f32x2 pairs.
// 32 steps per block, ONE barrier / cp wait / batched reduction per block.
// NEW: inner loop software-pipelined by one step — operands for step st+1
// are register-loaded before step st's FMAs, hiding the 29-cyc LDS latency.
// ---------------------------------------------------------------------------
__global__ void __launch_bounds__(256, 1) wkv_main(
    const float* __restrict__ r, const float* __restrict__ w,
    const float* __restrict__ k, const float* __restrict__ v,
    const float* __restrict__ init_state, float* __restrict__ state_out)
{
    extern __shared__ __align__(16) float smem[];
    float* stage = smem;                       // [NSTG][STAGE_F]
    float* partb = smem + NSTG * STAGE_F;      // [2][st][rg][36]

    const int tid  = threadIdx.x;
    const int bx   = blockIdx.x;
    const int by   = blockIdx.y;
    const int wid  = tid >> 5;
    const int lane = tid & 31;
    const int c    = lane & 3;
    const int rg   = lane >> 2;
    const int rg4  = rg * 4;
    const int col32 = wid * 4 + c;
    const int b    = bx * 32 + col32;
    const int a0   = by * 64 + rg * 8;

    const unsigned smem_u32 = (unsigned)__cvta_generic_to_shared(smem);

    // ---- cp.async roles: 1792 pieces per block, exactly 7 per thread
    const float* srcs[7];
    unsigned offs[7];
#pragma unroll
    for (int j = 0; j < 7; j++) {
        cp_role(tid + j * 256, r, w, k, v, bx, by, srcs[j], offs[j]);
        offs[j] = smem_u32 + offs[j] * 4u;
    }

    // ---- init state: state0[a][b] = init_state[b]
    const float is0 = init_state[b];
    ull s2[4];
    {
        ull iv = pk2(is0, is0);
#pragma unroll
        for (int i = 0; i < 4; i++) s2[i] = iv;
    }

    // ---- prologue: stage blocks 0,1
#pragma unroll
    for (int s = 0; s < 2; s++) {
        const size_t adv = (size_t)s * STEPS * DD;
        const unsigned bo = s * STAGE_B;
#pragma unroll
        for (int j = 0; j < 7; j++) CP16(offs[j] + bo, srcs[j] + adv);
        CP_COMMIT();
    }
#pragma unroll
    for (int j = 0; j < 7; j++) srcs[j] += (size_t)2 * STEPS * DD;
    CP_WAIT1();
    __syncthreads();

    // partial roles: writer (rg,col32) -> pp[st*288 + rg*36 + col32]
    const int wbase = rg * 36 + col32;
    float* gpr = g_part + (size_t)by * TT * DD + (size_t)bx * 32 + lane;
    const int vidx = 192 + col32;

    int gOff  = 0;                  // byte offset of compute buffer
    unsigned giOff = 2 * STAGE_B;   // byte offset of next issue buffer

    for (int blk = 0; blk < NBLK; blk++) {
        const int p = blk & 1;
        const char* sgb = (const char*)stage + gOff;
        float* pp = partb + p * PART_HALF;

        // software-pipelined step loop: load st+1 before computing st
        StepOps cur = load_step((const ull*)sgb, rg4, vidx);
#pragma unroll
        for (int st = 0; st < STEPS; st++) {
            StepOps nxt;
            if (st + 1 < STEPS)
                nxt = load_step((const ull*)(sgb + (st + 1) * (STEP_F * 4)), rg4, vidx);
            pp[st * 288 + wbase] = do_step(cur, s2);
            if (st + 1 < STEPS) cur = nxt;
        }

        // stage block blk+2
        if (blk + 2 < NBLK) {
#pragma unroll
            for (int j = 0; j < 7; j++) CP16(offs[j] + giOff, srcs[j]);
        }
#pragma unroll
        for (int j = 0; j < 7; j++) srcs[j] += STEPS * DD;
        CP_COMMIT();
        CP_WAIT1();
        __syncthreads();

        // batched reduction: thread handles (col=lane, st = wid + 8h), h=0..3
        {
            const size_t t0 = (size_t)blk * STEPS;
#pragma unroll
            for (int h = 0; h < 4; h++) {
                const int st = wid + h * 8;
                const float* pr = pp + st * 288 + lane;
                float acc = pr[0];
#pragma unroll
                for (int g = 1; g < 8; g++) acc += pr[g * 36];
                gpr[(t0 + st) * DD] = acc;
            }
        }

        gOff  = (gOff  == (NSTG - 1) * STAGE_B) ? 0 : gOff  + STAGE_B;
        giOff = (giOff == (NSTG - 1) * STAGE_B) ? 0 : giOff + STAGE_B;
    }

    // ---- final state write
    if (state_out) {
#pragma unroll
        for (int i = 0; i < 4; i++) {
            float lo, hi; up2(s2[i], lo, hi);
            state_out[(size_t)(a0 + 2 * i)     * DD + b] = lo;
            state_out[(size_t)(a0 + 2 * i + 1) * DD + b] = hi;
        }
    }
}

// ---------------------------------------------------------------------------
// Combine: y[t][b] = (sum_a r*u*k)*v[t][b] + sum of 8 row-block partials.
// ---------------------------------------------------------------------------
__global__ void __launch_bounds__(256) wkv_combine(
    const float* __restrict__ r, const float* __restrict__ k,
    const float* __restrict__ u, const float* __restrict__ v,
    float* __restrict__ y)
{
    const int t = blockIdx.x;
    const int tid = threadIdx.x;
    __shared__ float red[8];

    const float* rt = r + (size_t)t * DD;
    const float* kt = k + (size_t)t * DD;

    float p = rt[tid] * u[tid] * kt[tid]
            + rt[tid + 256] * u[tid + 256] * kt[tid + 256];
#pragma unroll
    for (int m = 16; m >= 1; m >>= 1) p += __shfl_xor_sync(0xffffffffu, p, m);
    if ((tid & 31) == 0) red[tid >> 5] = p;
    __syncthreads();

    float ruk = 0.f;
#pragma unroll
    for (int g = 0; g < 8; g++) ruk += red[g];

    const float2* v2 = (const float2*)(v + (size_t)t * DD);
    float2* y2 = (float2*)(y + (size_t)t * DD);
    float2 vv = v2[tid];
    float2 acc; acc.x = ruk * vv.x; acc.y = ruk * vv.y;
#pragma unroll
    for (int g = 0; g < 8; g++) {
        const float2* gp2 = (const float2*)(g_part + (size_t)g * TT * DD + (size_t)t * DD);
        float2 pv = gp2[tid];
        acc.x += pv.x; acc.y += pv.y;
    }
    y2[tid] = acc;
}

// ---------------------------------------------------------------------------
extern "C" void kernel_launch(void* const* d_in, const int* in_sizes, int n_in,
                              void* d_out, int out_size) {
    const float* r          = (const float*)d_in[0];
    const float* w          = (const float*)d_in[1];
    const float* k          = (const float*)d_in[2];
    const float* v          = (const float*)d_in[3];
    const float* init_state = (const float*)d_in[4];
    const float* u          = (const float*)d_in[5];
    float* out = (float*)d_out;

    const int NTD = TT * DD;   // 1048576
    const int NDD = DD * DD;   // 262144

    float* y  = nullptr;
    float* st = nullptr;
    if (out_size >= NTD) {
        y = out;
        if (out_size >= NTD + NDD) st = out + NTD;
    } else if (out_size == NDD) {
        st = out;
    }

    const int smem_bytes = SMEM_FLOATS * 4;    // 159744
    cudaFuncSetAttribute(wkv_main, cudaFuncAttributeMaxDynamicSharedMemorySize, smem_bytes);

    wkv_main<<<dim3(16, 8), 256, smem_bytes>>>(r, w, k, v, init_state, st);
    if (y) wkv_combine<<<TT, 256>>>(r, k, u, v, y);
}